// round 12
// baseline (speedup 1.0000x reference)
#include <cuda_runtime.h>
#include <math_constants.h>
#include <cstdint>

#define NMAX 40000
#define EMAX 640000
#define HDIM 128
#define DOUTC 64
#define GMAX 64

// ---------------- static scratch (no allocation allowed) ----------------
__device__ float g_dinv[NMAX];
__device__ float g_bsum[NMAX];           // row sums of normalized adjacency
__device__ int   g_count[NMAX];          // also reused as scatter cursor
__device__ int   g_offs[NMAX + 1];
__device__ int   g_csr[EMAX];
__device__ int   g_start[GMAX + 1];
__device__ float g_bufA[NMAX * HDIM];
__device__ float g_bufB[NMAX * HDIM];
__device__ float g_no[NMAX * DOUTC];
__device__ __align__(16) float g_v1[DOUTC];  // b2@W3c
__device__ __align__(16) float g_v2[DOUTC];  // b3@Wc + bp1@Wp2 + bp2
__device__ uint4 g_frag1[8 * 16 * 32];   // W1 bf16 hi/lo fragments (K=16 steps)
__device__ uint4 g_fragC[8 * 8 * 32];    // Wcomb bf16 hi/lo fragments

// ---------------- bf16 helpers ----------------
__device__ __forceinline__ uint32_t pack_bf16(float lo, float hi) {
    uint32_t r;
    asm("cvt.rn.bf16x2.f32 %0, %1, %2;" : "=r"(r) : "f"(hi), "f"(lo));
    return r;
}
__device__ __forceinline__ float bf16lo_f(uint32_t p) { return __uint_as_float(p << 16); }
__device__ __forceinline__ float bf16hi_f(uint32_t p) { return __uint_as_float(p & 0xffff0000u); }

__device__ __forceinline__ void split_pair(float x, float y, uint32_t& h, uint32_t& l) {
    h = pack_bf16(x, y);
    l = pack_bf16(x - bf16lo_f(h), y - bf16hi_f(h));
}

__device__ __forceinline__ void mma_bf16(float* c, uint32_t a0, uint32_t a1, uint32_t a2,
                                         uint32_t a3, uint32_t b0, uint32_t b1) {
    asm volatile(
        "mma.sync.aligned.m16n8k16.row.col.f32.bf16.bf16.f32 "
        "{%0,%1,%2,%3}, {%4,%5,%6,%7}, {%8,%9}, {%0,%1,%2,%3};"
        : "+f"(c[0]), "+f"(c[1]), "+f"(c[2]), "+f"(c[3])
        : "r"(a0), "r"(a1), "r"(a2), "r"(a3), "r"(b0), "r"(b1));
}

// Build one bf16 fragment entry for the B operand of m16n8k16 from row-major W.
__device__ __forceinline__ void build_frag(const float* __restrict__ W, uint4* __restrict__ frag,
                                           int idx, int OUTC, int NT) {
    int lane = idx & 31;
    int j = (idx >> 5) % NT;
    int kk = idx / (32 * NT);
    int g = lane >> 2, tig = lane & 3;
    int col = j * 8 + g;
    int k0 = kk * 16;
    float w00 = W[(k0 + 2 * tig) * OUTC + col];
    float w01 = W[(k0 + 2 * tig + 1) * OUTC + col];
    float w10 = W[(k0 + 2 * tig + 8) * OUTC + col];
    float w11 = W[(k0 + 2 * tig + 9) * OUTC + col];
    uint32_t bh0, bl0, bh1, bl1;
    split_pair(w00, w01, bh0, bl0);
    split_pair(w10, w11, bh1, bl1);
    uint4 v; v.x = bh0; v.y = bh1; v.z = bl0; v.w = bl1;
    frag[idx] = v;
}

// ---------------- small kernels ----------------
// W1 fragment build — tiny, runs first on the main stream so gemm128 starts at once.
__global__ void b1frag_kernel(const float* __restrict__ W1, uint4* __restrict__ frag1) {
    int idx = blockIdx.x * blockDim.x + threadIdx.x;
    if (idx < 8 * 16 * 32) build_frag(W1, frag1, idx, 128, 16);
}

__global__ void count_kernel(const int* __restrict__ dst, int E, int* __restrict__ count) {
    int e = blockIdx.x * blockDim.x + threadIdx.x;
    if (e < E) atomicAdd(&count[dst[e]], 1);
}

// Single-block scan over N counters; emits dinv; re-zeroes count -> scatter cursor.
__global__ void scan_kernel(int* __restrict__ count, int n, int E,
                            int* __restrict__ offs, float* __restrict__ dinv) {
    __shared__ int sm[1024];
    const int t = threadIdx.x;
    const int IPT = (NMAX + 1023) / 1024;   // 40
    int base = t * IPT;
    int tot = 0;
    for (int i = 0; i < IPT; i++) {
        int idx = base + i;
        if (idx < n) tot += count[idx];
    }
    sm[t] = tot;
    __syncthreads();
    for (int off = 1; off < 1024; off <<= 1) {
        int v = (t >= off) ? sm[t - off] : 0;
        __syncthreads();
        sm[t] += v;
        __syncthreads();
    }
    int run = sm[t] - tot;
    for (int i = 0; i < IPT; i++) {
        int idx = base + i;
        if (idx < n) {
            int c = count[idx];
            offs[idx] = run;
            run += c;
            dinv[idx] = rsqrtf((float)(c + 1));
            count[idx] = 0;
        }
    }
    if (t == 0) offs[n] = E;
}

__global__ void scatter_kernel(const int* __restrict__ src, const int* __restrict__ dst,
                               int E, const int* __restrict__ offs,
                               int* __restrict__ cursor, int* __restrict__ csr) {
    int e = blockIdx.x * blockDim.x + threadIdx.x;
    if (e < E) {
        int d = dst[e];
        int p = atomicAdd(&cursor[d], 1);
        csr[offs[d] + p] = src[e];
    }
}

// ---------------- fused weight-chain prep (column-separable) ------------------------
__global__ void prep_all_kernel(const float* __restrict__ Wp1, const float* __restrict__ bp1,
                                const float* __restrict__ Wp2, const float* __restrict__ bp2,
                                const float* __restrict__ W2, const float* __restrict__ b2,
                                const float* __restrict__ W3, const float* __restrict__ b3,
                                float* __restrict__ v1, float* __restrict__ v2,
                                uint4* __restrict__ fragC,
                                const int* __restrict__ batch, int n, int G,
                                int* __restrict__ start) {
    int b = blockIdx.x;
    if (b >= DOUTC) {
        int g = threadIdx.x;
        if (g <= G) {
            int lo = 0, hi = n;
            while (lo < hi) {
                int m = (lo + hi) >> 1;
                if (batch[m] < g) lo = m + 1; else hi = m;
            }
            start[g] = lo;
        }
        return;
    }
    int r = threadIdx.x;   // 0..127
    __shared__ float colA[128], colB[128];
    __shared__ float rA[128], rB[128], rC[128];

    float s = 0.f;
#pragma unroll 8
    for (int k = 0; k < HDIM; k++) s += Wp1[r * HDIM + k] * Wp2[k * DOUTC + b];
    colA[r] = s;
    rA[r] = bp1[r] * Wp2[r * DOUTC + b];
    __syncthreads();
    float s2 = 0.f;
#pragma unroll 8
    for (int k = 0; k < HDIM; k++) s2 += W3[r * HDIM + k] * colA[k];
    rB[r] = b3[r] * colA[r];
    colB[r] = s2;
    __syncthreads();
    float s3 = 0.f;
#pragma unroll 8
    for (int k = 0; k < HDIM; k++) s3 += W2[r * HDIM + k] * colB[k];
    rC[r] = b2[r] * colB[r];
    __syncthreads();
    colA[r] = s3;          // Wcomb[:,b]
    for (int o = 64; o; o >>= 1) {
        if (r < o) { rA[r] += rA[r + o]; rB[r] += rB[r + o]; rC[r] += rC[r + o]; }
        __syncthreads();
    }
    if (r == 0) { v1[b] = rC[0]; v2[b] = rB[0] + rA[0] + bp2[b]; }
    // fragC entries for this column (32 of them)
    if (r < 32) {
        int kk = r >> 2, tig = r & 3;
        int k0 = kk * 16;
        float w00 = colA[k0 + 2 * tig],     w01 = colA[k0 + 2 * tig + 1];
        float w10 = colA[k0 + 2 * tig + 8], w11 = colA[k0 + 2 * tig + 9];
        uint32_t bh0, bl0, bh1, bl1;
        split_pair(w00, w01, bh0, bl0);
        split_pair(w10, w11, bh1, bl1);
        uint4 v; v.x = bh0; v.y = bh1; v.z = bl0; v.w = bl1;
        fragC[(kk * 8 + (b >> 3)) * 32 + (((b & 7) << 2) | tig)] = v;
    }
}

// ---------------- bf16 tensor-core GEMM (3xBF16 split, m16n8k16) --------------------
template <int OUTC>
__global__ __launch_bounds__(256, 2) void mma_gemm_kernel(const float* __restrict__ A,
                                                          const uint4* __restrict__ fragG,
                                                          float* __restrict__ out, int n,
                                                          const float* __restrict__ rowScale) {
    constexpr int NT = OUTC / 8;
    constexpr int AP = 132;
    extern __shared__ float smem[];
    float* As = smem;

    const int tid = threadIdx.x;
    const int row0 = blockIdx.x * 128;

    for (int i = tid; i < 128 * 32; i += 256) {
        int r = i >> 5, c4 = (i & 31) << 2;
        int gr = row0 + r;
        float4 v = (gr < n) ? *(const float4*)(A + (size_t)gr * 128 + c4)
                            : make_float4(0.f, 0.f, 0.f, 0.f);
        *(float4*)(As + r * AP + c4) = v;
    }
    __syncthreads();

    const int wid = tid >> 5, lane = tid & 31;
    const int g = lane >> 2, tig = lane & 3;
    const int m0 = wid * 16;

    float acc[NT][4];
#pragma unroll
    for (int j = 0; j < NT; j++)
#pragma unroll
        for (int i = 0; i < 4; i++) acc[j][i] = 0.f;

    const float* r0p = As + (m0 + g) * AP;
    const float* r1p = As + (m0 + g + 8) * AP;
    const uint4* fbase = fragG + lane;

#pragma unroll 1
    for (int kk = 0; kk < 8; kk++) {
        const uint4* bf = fbase + (size_t)(kk * NT) * 32;
        uint4 bfr[NT];
#pragma unroll
        for (int j = 0; j < NT; j++) bfr[j] = __ldg(bf + j * 32);

        const int c0 = kk * 16 + 2 * tig;
        float2 p00 = *(const float2*)(r0p + c0);
        float2 p10 = *(const float2*)(r1p + c0);
        float2 p01 = *(const float2*)(r0p + c0 + 8);
        float2 p11 = *(const float2*)(r1p + c0 + 8);

        uint32_t ah0, al0, ah1, al1, ah2, al2, ah3, al3;
        split_pair(p00.x, p00.y, ah0, al0);
        split_pair(p10.x, p10.y, ah1, al1);
        split_pair(p01.x, p01.y, ah2, al2);
        split_pair(p11.x, p11.y, ah3, al3);

#pragma unroll
        for (int j = 0; j < NT; j++) {
            uint32_t bh0 = bfr[j].x, bh1 = bfr[j].y, bl0 = bfr[j].z, bl1 = bfr[j].w;
            mma_bf16(acc[j], ah0, ah1, ah2, ah3, bh0, bh1);
            mma_bf16(acc[j], ah0, ah1, ah2, ah3, bl0, bl1);
            mma_bf16(acc[j], al0, al1, al2, al3, bh0, bh1);
        }
    }

    const int r0 = row0 + m0 + g;
    const int r1 = r0 + 8;
    float s0 = 1.f, s1 = 1.f;
    if (rowScale) {
        if (r0 < n) s0 = rowScale[r0];
        if (r1 < n) s1 = rowScale[r1];
    }
#pragma unroll
    for (int j = 0; j < NT; j++) {
        int c = j * 8 + tig * 2;
        if (r0 < n) {
            float2 v; v.x = acc[j][0] * s0; v.y = acc[j][1] * s0;
            *(float2*)(out + (size_t)r0 * OUTC + c) = v;
        }
        if (r1 < n) {
            float2 v; v.x = acc[j][2] * s1; v.y = acc[j][3] * s1;
            *(float2*)(out + (size_t)r1 * OUTC + c) = v;
        }
    }
}

// ---------------- layer-1 aggregation + relu + LN1 + LN2 + bsum --------------------
__device__ __forceinline__ float warp_sum(float v) {
#pragma unroll
    for (int o = 16; o; o >>= 1) v += __shfl_xor_sync(0xffffffffu, v, o);
    return v;
}

__global__ void agg128_kernel(const float* __restrict__ t, const float* __restrict__ bias,
                              const float* __restrict__ g1, const float* __restrict__ b1,
                              const float* __restrict__ g2, const float* __restrict__ b2,
                              float* __restrict__ out, int n,
                              const int* __restrict__ offs, const int* __restrict__ csr,
                              const float* __restrict__ dinv, float* __restrict__ bsum) {
    int w = (blockIdx.x * blockDim.x + threadIdx.x) >> 5;
    if (w >= n) return;
    int lane = threadIdx.x & 31;
    int c0 = lane * 4;

    float di = dinv[w];
    float4 sv = *(const float4*)(t + (size_t)w * HDIM + c0);
    float4 acc;
    acc.x = di * sv.x; acc.y = di * sv.y; acc.z = di * sv.z; acc.w = di * sv.w;
    float dsum = 0.f;

    int e = offs[w], end = offs[w + 1];
    for (; e + 8 <= end; e += 8) {
        int s[8];
#pragma unroll
        for (int i = 0; i < 8; i++) s[i] = csr[e + i];
        float d[8];
#pragma unroll
        for (int i = 0; i < 8; i++) d[i] = dinv[s[i]];
        float4 v[8];
#pragma unroll
        for (int i = 0; i < 8; i++) v[i] = *(const float4*)(t + (size_t)s[i] * HDIM + c0);
#pragma unroll
        for (int i = 0; i < 8; i++) {
            dsum += d[i];
            acc.x += d[i] * v[i].x; acc.y += d[i] * v[i].y;
            acc.z += d[i] * v[i].z; acc.w += d[i] * v[i].w;
        }
    }
    for (; e < end; e++) {
        int s = csr[e];
        float ds = dinv[s];
        dsum += ds;
        float4 v = *(const float4*)(t + (size_t)s * HDIM + c0);
        acc.x += ds * v.x; acc.y += ds * v.y; acc.z += ds * v.z; acc.w += ds * v.w;
    }
    if (lane == 0) bsum[w] = di * (di + dsum);

    float4 bv = *(const float4*)(bias + c0);
    float4 h;
    h.x = bv.x + di * acc.x;
    h.y = bv.y + di * acc.y;
    h.z = bv.z + di * acc.z;
    h.w = bv.w + di * acc.w;

    h.x = fmaxf(h.x, 0.f); h.y = fmaxf(h.y, 0.f);
    h.z = fmaxf(h.z, 0.f); h.w = fmaxf(h.w, 0.f);
    const float inv = 1.f / 128.f, eps = 1e-5f;
    {
        float mu = warp_sum(h.x + h.y + h.z + h.w) * inv;
        float dx = h.x - mu, dy = h.y - mu, dz = h.z - mu, dw = h.w - mu;
        float var = warp_sum(dx * dx + dy * dy + dz * dz + dw * dw) * inv;
        float rs = rsqrtf(var + eps);
        float4 G = *(const float4*)(g1 + c0);
        float4 B = *(const float4*)(b1 + c0);
        h.x = dx * rs * G.x + B.x; h.y = dy * rs * G.y + B.y;
        h.z = dz * rs * G.z + B.z; h.w = dw * rs * G.w + B.w;
    }
    {
        float mu = warp_sum(h.x + h.y + h.z + h.w) * inv;
        float dx = h.x - mu, dy = h.y - mu, dz = h.z - mu, dw = h.w - mu;
        float var = warp_sum(dx * dx + dy * dy + dz * dz + dw * dw) * inv;
        float rs = rsqrtf(var + eps);
        float4 G = *(const float4*)(g2 + c0);
        float4 B = *(const float4*)(b2 + c0);
        h.x = dx * rs * G.x + B.x; h.y = dy * rs * G.y + B.y;
        h.z = dz * rs * G.z + B.z; h.w = dw * rs * G.w + B.w;
    }
    *(float4*)(out + (size_t)w * HDIM + c0) = h;
}

// ---------------- 64-dim aggregation (1 node/warp, float2 lanes, deep unroll) ------
// Inputs prescaled by dinv -> pure gather-sum. Epilogue:
//   FINAL=false: out[w] = dinv[w]^2 * sum   (keeps chain prescaled)
//   FINAL=true : out[w] = dinv[w]   * sum + bsum[w]*v1 + v2
template <bool FINAL>
__global__ void agg64_kernel(const float* __restrict__ t, float* __restrict__ out, int n,
                             const int* __restrict__ offs, const int* __restrict__ csr,
                             const float* __restrict__ dinv,
                             const float* __restrict__ bsum,
                             const float* __restrict__ v1, const float* __restrict__ v2) {
    int w = (blockIdx.x * blockDim.x + threadIdx.x) >> 5;
    if (w >= n) return;
    int lane = threadIdx.x & 31;
    int c0 = lane * 2;

    float2 acc = *(const float2*)(t + (size_t)w * DOUTC + c0);

    int e = offs[w], end = offs[w + 1];
    for (; e + 16 <= end; e += 16) {
        int s[16];
#pragma unroll
        for (int i = 0; i < 16; i++) s[i] = csr[e + i];
        float2 v[16];
#pragma unroll
        for (int i = 0; i < 16; i++) v[i] = *(const float2*)(t + (size_t)s[i] * DOUTC + c0);
#pragma unroll
        for (int i = 0; i < 16; i++) { acc.x += v[i].x; acc.y += v[i].y; }
    }
    for (; e + 4 <= end; e += 4) {
        int s0 = csr[e], s1 = csr[e + 1], s2 = csr[e + 2], s3 = csr[e + 3];
        float2 v0 = *(const float2*)(t + (size_t)s0 * DOUTC + c0);
        float2 a1 = *(const float2*)(t + (size_t)s1 * DOUTC + c0);
        float2 a2 = *(const float2*)(t + (size_t)s2 * DOUTC + c0);
        float2 a3 = *(const float2*)(t + (size_t)s3 * DOUTC + c0);
        acc.x += (v0.x + a1.x) + (a2.x + a3.x);
        acc.y += (v0.y + a1.y) + (a2.y + a3.y);
    }
    for (; e < end; e++) {
        int s = csr[e];
        float2 v = *(const float2*)(t + (size_t)s * DOUTC + c0);
        acc.x += v.x; acc.y += v.y;
    }

    float di = dinv[w];
    float2 h;
    if (FINAL) {
        float bs = bsum[w];
        float2 a = *(const float2*)(v1 + c0);
        float2 b = *(const float2*)(v2 + c0);
        h.x = di * acc.x + bs * a.x + b.x;
        h.y = di * acc.y + bs * a.y + b.y;
    } else {
        float d2 = di * di;
        h.x = d2 * acc.x;
        h.y = d2 * acc.y;
    }
    *(float2*)(out + (size_t)w * DOUTC + c0) = h;
}

// ---------------- fused pooling (max+mean) + log_softmax ---------------------------
__global__ void pool_softmax_kernel(const float* __restrict__ no,
                                    const int* __restrict__ start,
                                    float* __restrict__ out) {
    __shared__ float sv[128];
    __shared__ float sred[256];
    __shared__ float wred[8];
    int g = blockIdx.x;
    int beg = start[g], end = start[g + 1];
    int tid = threadIdx.x;
    int c = tid & 63, sub = tid >> 6;

    float mx = -CUDART_INF_F, sm = 0.f;
    for (int i = beg + sub; i < end; i += 4) {
        float v = no[(size_t)i * DOUTC + c];
        mx = fmaxf(mx, v);
        sm += v;
    }
    sred[tid] = mx;
    __syncthreads();
    float m4 = 0.f;
    if (sub == 0)
        m4 = fmaxf(fmaxf(sred[c], sred[c + 64]), fmaxf(sred[c + 128], sred[c + 192]));
    __syncthreads();
    sred[tid] = sm;
    __syncthreads();
    if (sub == 0) {
        float s4 = sred[c] + sred[c + 64] + sred[c + 128] + sred[c + 192];
        float cnt = (float)(end - beg);
        sv[c] = m4;
        sv[64 + c] = s4 / fmaxf(cnt, 1.f);
    }
    __syncthreads();

    float v = (tid < 128) ? sv[tid] : -CUDART_INF_F;
    float m = v;
#pragma unroll
    for (int o = 16; o; o >>= 1) m = fmaxf(m, __shfl_xor_sync(0xffffffffu, m, o));
    if ((tid & 31) == 0) wred[tid >> 5] = m;
    __syncthreads();
    if (tid == 0) {
        float mm = wred[0];
        for (int i = 1; i < 8; i++) mm = fmaxf(mm, wred[i]);
        wred[0] = mm;
    }
    __syncthreads();
    float M = wred[0];
    __syncthreads();
    float e = (tid < 128) ? expf(v - M) : 0.f;
    float s = e;
#pragma unroll
    for (int o = 16; o; o >>= 1) s += __shfl_xor_sync(0xffffffffu, s, o);
    if ((tid & 31) == 0) wred[tid >> 5] = s;
    __syncthreads();
    if (tid == 0) {
        float ss = 0.f;
        for (int i = 0; i < 8; i++) ss += wred[i];
        wred[0] = ss;
    }
    __syncthreads();
    float S = wred[0];
    if (tid < 128) out[g * 128 + tid] = v - M - logf(S);
}

// ---------------- host orchestration ----------------
extern "C" void kernel_launch(void* const* d_in, const int* in_sizes, int n_in,
                              void* d_out, int out_size) {
    const float* x   = (const float*)d_in[0];
    const int*   ei  = (const int*)d_in[1];
    const int*   bat = (const int*)d_in[2];
    const float* W1  = (const float*)d_in[3];
    const float* b1  = (const float*)d_in[4];
    const float* ln1g = (const float*)d_in[5];
    const float* ln1b = (const float*)d_in[6];
    const float* ln2g = (const float*)d_in[7];
    const float* ln2b = (const float*)d_in[8];
    const float* W2  = (const float*)d_in[9];
    const float* b2  = (const float*)d_in[10];
    const float* W3  = (const float*)d_in[11];
    const float* b3  = (const float*)d_in[12];
    const float* Wp1 = (const float*)d_in[13];
    const float* bp1 = (const float*)d_in[14];
    const float* Wp2 = (const float*)d_in[15];
    const float* bp2 = (const float*)d_in[16];
    float* out = (float*)d_out;

    const int N = in_sizes[0] / HDIM;
    const int E = in_sizes[1] / 2;
    const int G = out_size / (2 * DOUTC);
    const int* src = ei;
    const int* dst = ei + E;

    float *dinv, *bsum, *bufA, *bufB, *no, *v1, *v2;
    uint4 *frag1, *fragC;
    int *count, *offs, *csr, *start;
    cudaGetSymbolAddress((void**)&dinv,  g_dinv);
    cudaGetSymbolAddress((void**)&bsum,  g_bsum);
    cudaGetSymbolAddress((void**)&count, g_count);
    cudaGetSymbolAddress((void**)&offs,  g_offs);
    cudaGetSymbolAddress((void**)&csr,   g_csr);
    cudaGetSymbolAddress((void**)&start, g_start);
    cudaGetSymbolAddress((void**)&bufA,  g_bufA);
    cudaGetSymbolAddress((void**)&bufB,  g_bufB);
    cudaGetSymbolAddress((void**)&no,    g_no);
    cudaGetSymbolAddress((void**)&v1,    g_v1);
    cudaGetSymbolAddress((void**)&v2,    g_v2);
    cudaGetSymbolAddress((void**)&frag1, g_frag1);
    cudaGetSymbolAddress((void**)&fragC, g_fragC);

    const int smemA = 128 * 132 * 4;   // 67584 B

    static cudaStream_t sB = nullptr;
    static cudaEvent_t evFork, evCsr, evPrep;
    if (!sB) {
        cudaFuncSetAttribute(mma_gemm_kernel<128>,
                             cudaFuncAttributeMaxDynamicSharedMemorySize, smemA);
        cudaFuncSetAttribute(mma_gemm_kernel<64>,
                             cudaFuncAttributeMaxDynamicSharedMemorySize, smemA);
        cudaStreamCreateWithFlags(&sB, cudaStreamNonBlocking);
        cudaEventCreateWithFlags(&evFork, cudaEventDisableTiming);
        cudaEventCreateWithFlags(&evCsr,  cudaEventDisableTiming);
        cudaEventCreateWithFlags(&evPrep, cudaEventDisableTiming);
    }

    const int gemmBlocks = (N + 127) / 128;
    const int agg128Blocks = (N * 32 + 255) / 256;
    const int agg64Blocks = (N * 32 + 255) / 256;
    const int countBlocks = (E + 255) / 256;

    // fork side stream from the captured (legacy) stream
    cudaEventRecord(evFork, 0);
    cudaStreamWaitEvent(sB, evFork, 0);

    // side stream: CSR build
    cudaMemsetAsync(count, 0, N * sizeof(int), sB);
    count_kernel<<<countBlocks, 256, 0, sB>>>(dst, E, count);
    scan_kernel<<<1, 1024, 0, sB>>>(count, N, E, offs, dinv);
    scatter_kernel<<<countBlocks, 256, 0, sB>>>(src, dst, E, offs, count, csr);
    cudaEventRecord(evCsr, sB);

    // main stream: W1 fragments (tiny) then layer-1 GEMM immediately — no CSR wait
    b1frag_kernel<<<16, 256>>>(W1, frag1);
    mma_gemm_kernel<128><<<gemmBlocks, 256, smemA>>>(x, frag1, bufA, N, nullptr);

    // side stream: fused weight-chain collapse
    prep_all_kernel<<<DOUTC + 1, 128, 0, sB>>>(Wp1, bp1, Wp2, bp2, W2, b2, W3, b3,
                                               v1, v2, fragC, bat, N, G, start);
    cudaEventRecord(evPrep, sB);

    // main stream: aggregation chain
    cudaStreamWaitEvent(0, evCsr, 0);
    agg128_kernel<<<agg128Blocks, 256>>>(bufA, b1, ln1g, ln1b, ln2g, ln2b,
                                         bufB, N, offs, csr, dinv, bsum);
    cudaStreamWaitEvent(0, evPrep, 0);
    // gemm64 writes rows pre-scaled by dinv for the pure-sum agg chain
    mma_gemm_kernel<64><<<gemmBlocks, 256, smemA>>>(bufB, fragC, no, N, dinv);
    agg64_kernel<false><<<agg64Blocks, 256>>>(no, bufA, N, offs, csr, dinv,
                                              nullptr, nullptr, nullptr);
    agg64_kernel<true><<<agg64Blocks, 256>>>(bufA, no, N, offs, csr, dinv,
                                             bsum, v1, v2);

    // pooling + log_softmax
    pool_softmax_kernel<<<G, 256>>>(no, start, out);
}

// round 13
// speedup vs baseline: 1.0763x; 1.0763x over previous
#include <cuda_runtime.h>
#include <math_constants.h>
#include <cstdint>

#define NMAX 40000
#define EMAX 640000
#define HDIM 128
#define DOUTC 64
#define GMAX 64

// ---------------- static scratch (no allocation allowed) ----------------
__device__ float g_dinv[NMAX];
__device__ float g_bsum[NMAX];           // row sums of normalized adjacency
__device__ int   g_count[NMAX];          // also reused as scatter cursor
__device__ int   g_offs[NMAX + 1];
__device__ int   g_csr[EMAX];
__device__ int   g_start[GMAX + 1];
__device__ float g_bufA[NMAX * HDIM];
__device__ float g_bufB[NMAX * HDIM];
__device__ float g_no[NMAX * DOUTC];
__device__ __align__(16) float g_v1[DOUTC];  // b2@W3c
__device__ __align__(16) float g_v2[DOUTC];  // b3@Wc + bp1@Wp2 + bp2
__device__ uint4 g_frag1[8 * 16 * 32];   // W1 bf16 hi/lo fragments (K=16 steps)
__device__ uint4 g_fragC[8 * 8 * 32];    // Wcomb bf16 hi/lo fragments

// ---------------- bf16 helpers ----------------
__device__ __forceinline__ uint32_t pack_bf16(float lo, float hi) {
    uint32_t r;
    asm("cvt.rn.bf16x2.f32 %0, %1, %2;" : "=r"(r) : "f"(hi), "f"(lo));
    return r;
}
__device__ __forceinline__ float bf16lo_f(uint32_t p) { return __uint_as_float(p << 16); }
__device__ __forceinline__ float bf16hi_f(uint32_t p) { return __uint_as_float(p & 0xffff0000u); }

__device__ __forceinline__ void split_pair(float x, float y, uint32_t& h, uint32_t& l) {
    h = pack_bf16(x, y);
    l = pack_bf16(x - bf16lo_f(h), y - bf16hi_f(h));
}

__device__ __forceinline__ void mma_bf16(float* c, uint32_t a0, uint32_t a1, uint32_t a2,
                                         uint32_t a3, uint32_t b0, uint32_t b1) {
    asm volatile(
        "mma.sync.aligned.m16n8k16.row.col.f32.bf16.bf16.f32 "
        "{%0,%1,%2,%3}, {%4,%5,%6,%7}, {%8,%9}, {%0,%1,%2,%3};"
        : "+f"(c[0]), "+f"(c[1]), "+f"(c[2]), "+f"(c[3])
        : "r"(a0), "r"(a1), "r"(a2), "r"(a3), "r"(b0), "r"(b1));
}

// Build one bf16 fragment entry for the B operand of m16n8k16 from row-major W.
__device__ __forceinline__ void build_frag(const float* __restrict__ W, uint4* __restrict__ frag,
                                           int idx, int OUTC, int NT) {
    int lane = idx & 31;
    int j = (idx >> 5) % NT;
    int kk = idx / (32 * NT);
    int g = lane >> 2, tig = lane & 3;
    int col = j * 8 + g;
    int k0 = kk * 16;
    float w00 = W[(k0 + 2 * tig) * OUTC + col];
    float w01 = W[(k0 + 2 * tig + 1) * OUTC + col];
    float w10 = W[(k0 + 2 * tig + 8) * OUTC + col];
    float w11 = W[(k0 + 2 * tig + 9) * OUTC + col];
    uint32_t bh0, bl0, bh1, bl1;
    split_pair(w00, w01, bh0, bl0);
    split_pair(w10, w11, bh1, bl1);
    uint4 v; v.x = bh0; v.y = bh1; v.z = bl0; v.w = bl1;
    frag[idx] = v;
}

// ---------------- CSR build kernels (R9 order) ----------------
// blocks [0, countBlocks): degree count; blocks beyond: build W1 fragments
__global__ void count_frag_kernel(const int* __restrict__ dst, int E, int* __restrict__ count,
                                  int countBlocks, const float* __restrict__ W1,
                                  uint4* __restrict__ frag1) {
    if ((int)blockIdx.x < countBlocks) {
        int e = blockIdx.x * blockDim.x + threadIdx.x;
        if (e < E) atomicAdd(&count[dst[e]], 1);
    } else {
        int idx = (blockIdx.x - countBlocks) * blockDim.x + threadIdx.x;
        if (idx < 8 * 16 * 32) build_frag(W1, frag1, idx, 128, 16);
    }
}

// Single-block scan over N counters; emits dinv; re-zeroes count -> scatter cursor.
__global__ void scan_kernel(int* __restrict__ count, int n, int E,
                            int* __restrict__ offs, float* __restrict__ dinv) {
    __shared__ int sm[1024];
    const int t = threadIdx.x;
    const int IPT = (NMAX + 1023) / 1024;   // 40
    int base = t * IPT;
    int tot = 0;
    for (int i = 0; i < IPT; i++) {
        int idx = base + i;
        if (idx < n) tot += count[idx];
    }
    sm[t] = tot;
    __syncthreads();
    for (int off = 1; off < 1024; off <<= 1) {
        int v = (t >= off) ? sm[t - off] : 0;
        __syncthreads();
        sm[t] += v;
        __syncthreads();
    }
    int run = sm[t] - tot;
    for (int i = 0; i < IPT; i++) {
        int idx = base + i;
        if (idx < n) {
            int c = count[idx];
            offs[idx] = run;
            run += c;
            dinv[idx] = rsqrtf((float)(c + 1));
            count[idx] = 0;
        }
    }
    if (t == 0) offs[n] = E;
}

__global__ void scatter_kernel(const int* __restrict__ src, const int* __restrict__ dst,
                               int E, const int* __restrict__ offs,
                               int* __restrict__ cursor, int* __restrict__ csr) {
    int e = blockIdx.x * blockDim.x + threadIdx.x;
    if (e < E) {
        int d = dst[e];
        int p = atomicAdd(&cursor[d], 1);
        csr[offs[d] + p] = src[e];
    }
}

// bsum[w] = dinv[w]*(dinv[w] + sum_s dinv[csr[e]]) — warp per node, lane-strided.
__global__ void bsum_kernel(const int* __restrict__ offs, const int* __restrict__ csr,
                            const float* __restrict__ dinv, float* __restrict__ bsum, int n) {
    int w = (blockIdx.x * blockDim.x + threadIdx.x) >> 5;
    if (w >= n) return;
    int lane = threadIdx.x & 31;
    int e = offs[w], end = offs[w + 1];
    float s = 0.f;
    for (int i = e + lane; i < end; i += 32) s += dinv[csr[i]];
#pragma unroll
    for (int o = 16; o; o >>= 1) s += __shfl_xor_sync(0xffffffffu, s, o);
    if (lane == 0) {
        float di = dinv[w];
        bsum[w] = di * (di + s);
    }
}

// ---------------- fused weight-chain prep (column-separable) ------------------------
__global__ void prep_all_kernel(const float* __restrict__ Wp1, const float* __restrict__ bp1,
                                const float* __restrict__ Wp2, const float* __restrict__ bp2,
                                const float* __restrict__ W2, const float* __restrict__ b2,
                                const float* __restrict__ W3, const float* __restrict__ b3,
                                float* __restrict__ v1, float* __restrict__ v2,
                                uint4* __restrict__ fragC,
                                const int* __restrict__ batch, int n, int G,
                                int* __restrict__ start) {
    int b = blockIdx.x;
    if (b >= DOUTC) {
        int g = threadIdx.x;
        if (g <= G) {
            int lo = 0, hi = n;
            while (lo < hi) {
                int m = (lo + hi) >> 1;
                if (batch[m] < g) lo = m + 1; else hi = m;
            }
            start[g] = lo;
        }
        return;
    }
    int r = threadIdx.x;   // 0..127
    __shared__ float colA[128], colB[128];
    __shared__ float rA[128], rB[128], rC[128];

    float s = 0.f;
#pragma unroll 8
    for (int k = 0; k < HDIM; k++) s += Wp1[r * HDIM + k] * Wp2[k * DOUTC + b];
    colA[r] = s;
    rA[r] = bp1[r] * Wp2[r * DOUTC + b];
    __syncthreads();
    float s2 = 0.f;
#pragma unroll 8
    for (int k = 0; k < HDIM; k++) s2 += W3[r * HDIM + k] * colA[k];
    rB[r] = b3[r] * colA[r];
    colB[r] = s2;
    __syncthreads();
    float s3 = 0.f;
#pragma unroll 8
    for (int k = 0; k < HDIM; k++) s3 += W2[r * HDIM + k] * colB[k];
    rC[r] = b2[r] * colB[r];
    __syncthreads();
    colA[r] = s3;          // Wcomb[:,b]
    for (int o = 64; o; o >>= 1) {
        if (r < o) { rA[r] += rA[r + o]; rB[r] += rB[r + o]; rC[r] += rC[r + o]; }
        __syncthreads();
    }
    if (r == 0) { v1[b] = rC[0]; v2[b] = rB[0] + rA[0] + bp2[b]; }
    // fragC entries for this column (32 of them)
    if (r < 32) {
        int kk = r >> 2, tig = r & 3;
        int k0 = kk * 16;
        float w00 = colA[k0 + 2 * tig],     w01 = colA[k0 + 2 * tig + 1];
        float w10 = colA[k0 + 2 * tig + 8], w11 = colA[k0 + 2 * tig + 9];
        uint32_t bh0, bl0, bh1, bl1;
        split_pair(w00, w01, bh0, bl0);
        split_pair(w10, w11, bh1, bl1);
        uint4 v; v.x = bh0; v.y = bh1; v.z = bl0; v.w = bl1;
        fragC[(kk * 8 + (b >> 3)) * 32 + (((b & 7) << 2) | tig)] = v;
    }
}

// ---------------- bf16 tensor-core GEMM (3xBF16 split, m16n8k16) --------------------
template <int OUTC>
__global__ __launch_bounds__(256, 2) void mma_gemm_kernel(const float* __restrict__ A,
                                                          const uint4* __restrict__ fragG,
                                                          float* __restrict__ out, int n,
                                                          const float* __restrict__ rowScale) {
    constexpr int NT = OUTC / 8;
    constexpr int AP = 132;
    extern __shared__ float smem[];
    float* As = smem;

    const int tid = threadIdx.x;
    const int row0 = blockIdx.x * 128;

    for (int i = tid; i < 128 * 32; i += 256) {
        int r = i >> 5, c4 = (i & 31) << 2;
        int gr = row0 + r;
        float4 v = (gr < n) ? *(const float4*)(A + (size_t)gr * 128 + c4)
                            : make_float4(0.f, 0.f, 0.f, 0.f);
        *(float4*)(As + r * AP + c4) = v;
    }
    __syncthreads();

    const int wid = tid >> 5, lane = tid & 31;
    const int g = lane >> 2, tig = lane & 3;
    const int m0 = wid * 16;

    float acc[NT][4];
#pragma unroll
    for (int j = 0; j < NT; j++)
#pragma unroll
        for (int i = 0; i < 4; i++) acc[j][i] = 0.f;

    const float* r0p = As + (m0 + g) * AP;
    const float* r1p = As + (m0 + g + 8) * AP;
    const uint4* fbase = fragG + lane;

#pragma unroll 1
    for (int kk = 0; kk < 8; kk++) {
        const uint4* bf = fbase + (size_t)(kk * NT) * 32;
        uint4 bfr[NT];
#pragma unroll
        for (int j = 0; j < NT; j++) bfr[j] = __ldg(bf + j * 32);

        const int c0 = kk * 16 + 2 * tig;
        float2 p00 = *(const float2*)(r0p + c0);
        float2 p10 = *(const float2*)(r1p + c0);
        float2 p01 = *(const float2*)(r0p + c0 + 8);
        float2 p11 = *(const float2*)(r1p + c0 + 8);

        uint32_t ah0, al0, ah1, al1, ah2, al2, ah3, al3;
        split_pair(p00.x, p00.y, ah0, al0);
        split_pair(p10.x, p10.y, ah1, al1);
        split_pair(p01.x, p01.y, ah2, al2);
        split_pair(p11.x, p11.y, ah3, al3);

#pragma unroll
        for (int j = 0; j < NT; j++) {
            uint32_t bh0 = bfr[j].x, bh1 = bfr[j].y, bl0 = bfr[j].z, bl1 = bfr[j].w;
            mma_bf16(acc[j], ah0, ah1, ah2, ah3, bh0, bh1);
            mma_bf16(acc[j], ah0, ah1, ah2, ah3, bl0, bl1);
            mma_bf16(acc[j], al0, al1, al2, al3, bh0, bh1);
        }
    }

    const int r0 = row0 + m0 + g;
    const int r1 = r0 + 8;
    float s0 = 1.f, s1 = 1.f;
    if (rowScale) {
        if (r0 < n) s0 = rowScale[r0];
        if (r1 < n) s1 = rowScale[r1];
    }
#pragma unroll
    for (int j = 0; j < NT; j++) {
        int c = j * 8 + tig * 2;
        if (r0 < n) {
            float2 v; v.x = acc[j][0] * s0; v.y = acc[j][1] * s0;
            *(float2*)(out + (size_t)r0 * OUTC + c) = v;
        }
        if (r1 < n) {
            float2 v; v.x = acc[j][2] * s1; v.y = acc[j][3] * s1;
            *(float2*)(out + (size_t)r1 * OUTC + c) = v;
        }
    }
}

// ---------------- layer-1 aggregation (prescaled input) + relu + LN1 + LN2 ---------
// Input t is prescaled by dinv (gemm128 rowScale), so the inner loop is a pure
// float4 gather-sum; out[w] = bias + dinv[w]*(t'[w] + sum_s t'[s]), then relu+2xLN.
__device__ __forceinline__ float warp_sum(float v) {
#pragma unroll
    for (int o = 16; o; o >>= 1) v += __shfl_xor_sync(0xffffffffu, v, o);
    return v;
}

__global__ void agg128_kernel(const float* __restrict__ t, const float* __restrict__ bias,
                              const float* __restrict__ g1, const float* __restrict__ b1,
                              const float* __restrict__ g2, const float* __restrict__ b2,
                              float* __restrict__ out, int n,
                              const int* __restrict__ offs, const int* __restrict__ csr,
                              const float* __restrict__ dinv) {
    int w = (blockIdx.x * blockDim.x + threadIdx.x) >> 5;
    if (w >= n) return;
    int lane = threadIdx.x & 31;
    int c0 = lane * 4;

    float4 acc = *(const float4*)(t + (size_t)w * HDIM + c0);   // self (prescaled)

    int e = offs[w], end = offs[w + 1];
    for (; e + 8 <= end; e += 8) {
        int s[8];
#pragma unroll
        for (int i = 0; i < 8; i++) s[i] = csr[e + i];
        float4 v[8];
#pragma unroll
        for (int i = 0; i < 8; i++) v[i] = *(const float4*)(t + (size_t)s[i] * HDIM + c0);
#pragma unroll
        for (int i = 0; i < 8; i++) {
            acc.x += v[i].x; acc.y += v[i].y; acc.z += v[i].z; acc.w += v[i].w;
        }
    }
    for (; e < end; e++) {
        int s = csr[e];
        float4 v = *(const float4*)(t + (size_t)s * HDIM + c0);
        acc.x += v.x; acc.y += v.y; acc.z += v.z; acc.w += v.w;
    }

    float di = dinv[w];
    float4 bv = *(const float4*)(bias + c0);
    float4 h;
    h.x = bv.x + di * acc.x;
    h.y = bv.y + di * acc.y;
    h.z = bv.z + di * acc.z;
    h.w = bv.w + di * acc.w;

    h.x = fmaxf(h.x, 0.f); h.y = fmaxf(h.y, 0.f);
    h.z = fmaxf(h.z, 0.f); h.w = fmaxf(h.w, 0.f);
    const float inv = 1.f / 128.f, eps = 1e-5f;
    {
        float mu = warp_sum(h.x + h.y + h.z + h.w) * inv;
        float dx = h.x - mu, dy = h.y - mu, dz = h.z - mu, dw = h.w - mu;
        float var = warp_sum(dx * dx + dy * dy + dz * dz + dw * dw) * inv;
        float rs = rsqrtf(var + eps);
        float4 G = *(const float4*)(g1 + c0);
        float4 B = *(const float4*)(b1 + c0);
        h.x = dx * rs * G.x + B.x; h.y = dy * rs * G.y + B.y;
        h.z = dz * rs * G.z + B.z; h.w = dw * rs * G.w + B.w;
    }
    {
        float mu = warp_sum(h.x + h.y + h.z + h.w) * inv;
        float dx = h.x - mu, dy = h.y - mu, dz = h.z - mu, dw = h.w - mu;
        float var = warp_sum(dx * dx + dy * dy + dz * dz + dw * dw) * inv;
        float rs = rsqrtf(var + eps);
        float4 G = *(const float4*)(g2 + c0);
        float4 B = *(const float4*)(b2 + c0);
        h.x = dx * rs * G.x + B.x; h.y = dy * rs * G.y + B.y;
        h.z = dz * rs * G.z + B.z; h.w = dw * rs * G.w + B.w;
    }
    *(float4*)(out + (size_t)w * HDIM + c0) = h;
}

// ---------------- 64-dim aggregation (1 node/warp, float2 lanes, deep unroll) ------
template <bool FINAL>
__global__ void agg64_kernel(const float* __restrict__ t, float* __restrict__ out, int n,
                             const int* __restrict__ offs, const int* __restrict__ csr,
                             const float* __restrict__ dinv,
                             const float* __restrict__ bsum,
                             const float* __restrict__ v1, const float* __restrict__ v2) {
    int w = (blockIdx.x * blockDim.x + threadIdx.x) >> 5;
    if (w >= n) return;
    int lane = threadIdx.x & 31;
    int c0 = lane * 2;

    float2 acc = *(const float2*)(t + (size_t)w * DOUTC + c0);

    int e = offs[w], end = offs[w + 1];
    for (; e + 16 <= end; e += 16) {
        int s[16];
#pragma unroll
        for (int i = 0; i < 16; i++) s[i] = csr[e + i];
        float2 v[16];
#pragma unroll
        for (int i = 0; i < 16; i++) v[i] = *(const float2*)(t + (size_t)s[i] * DOUTC + c0);
#pragma unroll
        for (int i = 0; i < 16; i++) { acc.x += v[i].x; acc.y += v[i].y; }
    }
    for (; e + 4 <= end; e += 4) {
        int s0 = csr[e], s1 = csr[e + 1], s2 = csr[e + 2], s3 = csr[e + 3];
        float2 v0 = *(const float2*)(t + (size_t)s0 * DOUTC + c0);
        float2 a1 = *(const float2*)(t + (size_t)s1 * DOUTC + c0);
        float2 a2 = *(const float2*)(t + (size_t)s2 * DOUTC + c0);
        float2 a3 = *(const float2*)(t + (size_t)s3 * DOUTC + c0);
        acc.x += (v0.x + a1.x) + (a2.x + a3.x);
        acc.y += (v0.y + a1.y) + (a2.y + a3.y);
    }
    for (; e < end; e++) {
        int s = csr[e];
        float2 v = *(const float2*)(t + (size_t)s * DOUTC + c0);
        acc.x += v.x; acc.y += v.y;
    }

    float di = dinv[w];
    float2 h;
    if (FINAL) {
        float bs = bsum[w];
        float2 a = *(const float2*)(v1 + c0);
        float2 b = *(const float2*)(v2 + c0);
        h.x = di * acc.x + bs * a.x + b.x;
        h.y = di * acc.y + bs * a.y + b.y;
    } else {
        float d2 = di * di;
        h.x = d2 * acc.x;
        h.y = d2 * acc.y;
    }
    *(float2*)(out + (size_t)w * DOUTC + c0) = h;
}

// ---------------- fused pooling (max+mean) + log_softmax ---------------------------
__global__ void pool_softmax_kernel(const float* __restrict__ no,
                                    const int* __restrict__ start,
                                    float* __restrict__ out) {
    __shared__ float sv[128];
    __shared__ float sred[256];
    __shared__ float wred[8];
    int g = blockIdx.x;
    int beg = start[g], end = start[g + 1];
    int tid = threadIdx.x;
    int c = tid & 63, sub = tid >> 6;

    float mx = -CUDART_INF_F, sm = 0.f;
    for (int i = beg + sub; i < end; i += 4) {
        float v = no[(size_t)i * DOUTC + c];
        mx = fmaxf(mx, v);
        sm += v;
    }
    sred[tid] = mx;
    __syncthreads();
    float m4 = 0.f;
    if (sub == 0)
        m4 = fmaxf(fmaxf(sred[c], sred[c + 64]), fmaxf(sred[c + 128], sred[c + 192]));
    __syncthreads();
    sred[tid] = sm;
    __syncthreads();
    if (sub == 0) {
        float s4 = sred[c] + sred[c + 64] + sred[c + 128] + sred[c + 192];
        float cnt = (float)(end - beg);
        sv[c] = m4;
        sv[64 + c] = s4 / fmaxf(cnt, 1.f);
    }
    __syncthreads();

    float v = (tid < 128) ? sv[tid] : -CUDART_INF_F;
    float m = v;
#pragma unroll
    for (int o = 16; o; o >>= 1) m = fmaxf(m, __shfl_xor_sync(0xffffffffu, m, o));
    if ((tid & 31) == 0) wred[tid >> 5] = m;
    __syncthreads();
    if (tid == 0) {
        float mm = wred[0];
        for (int i = 1; i < 8; i++) mm = fmaxf(mm, wred[i]);
        wred[0] = mm;
    }
    __syncthreads();
    float M = wred[0];
    __syncthreads();
    float e = (tid < 128) ? expf(v - M) : 0.f;
    float s = e;
#pragma unroll
    for (int o = 16; o; o >>= 1) s += __shfl_xor_sync(0xffffffffu, s, o);
    if ((tid & 31) == 0) wred[tid >> 5] = s;
    __syncthreads();
    if (tid == 0) {
        float ss = 0.f;
        for (int i = 0; i < 8; i++) ss += wred[i];
        wred[0] = ss;
    }
    __syncthreads();
    float S = wred[0];
    if (tid < 128) out[g * 128 + tid] = v - M - logf(S);
}

// ---------------- host orchestration ----------------
extern "C" void kernel_launch(void* const* d_in, const int* in_sizes, int n_in,
                              void* d_out, int out_size) {
    const float* x   = (const float*)d_in[0];
    const int*   ei  = (const int*)d_in[1];
    const int*   bat = (const int*)d_in[2];
    const float* W1  = (const float*)d_in[3];
    const float* b1  = (const float*)d_in[4];
    const float* ln1g = (const float*)d_in[5];
    const float* ln1b = (const float*)d_in[6];
    const float* ln2g = (const float*)d_in[7];
    const float* ln2b = (const float*)d_in[8];
    const float* W2  = (const float*)d_in[9];
    const float* b2  = (const float*)d_in[10];
    const float* W3  = (const float*)d_in[11];
    const float* b3  = (const float*)d_in[12];
    const float* Wp1 = (const float*)d_in[13];
    const float* bp1 = (const float*)d_in[14];
    const float* Wp2 = (const float*)d_in[15];
    const float* bp2 = (const float*)d_in[16];
    float* out = (float*)d_out;

    const int N = in_sizes[0] / HDIM;
    const int E = in_sizes[1] / 2;
    const int G = out_size / (2 * DOUTC);
    const int* src = ei;
    const int* dst = ei + E;

    float *dinv, *bsum, *bufA, *bufB, *no, *v1, *v2;
    uint4 *frag1, *fragC;
    int *count, *offs, *csr, *start;
    cudaGetSymbolAddress((void**)&dinv,  g_dinv);
    cudaGetSymbolAddress((void**)&bsum,  g_bsum);
    cudaGetSymbolAddress((void**)&count, g_count);
    cudaGetSymbolAddress((void**)&offs,  g_offs);
    cudaGetSymbolAddress((void**)&csr,   g_csr);
    cudaGetSymbolAddress((void**)&start, g_start);
    cudaGetSymbolAddress((void**)&bufA,  g_bufA);
    cudaGetSymbolAddress((void**)&bufB,  g_bufB);
    cudaGetSymbolAddress((void**)&no,    g_no);
    cudaGetSymbolAddress((void**)&v1,    g_v1);
    cudaGetSymbolAddress((void**)&v2,    g_v2);
    cudaGetSymbolAddress((void**)&frag1, g_frag1);
    cudaGetSymbolAddress((void**)&fragC, g_fragC);

    const int smemA = 128 * 132 * 4;   // 67584 B

    static cudaStream_t sB = nullptr;
    static cudaEvent_t evFork, evScan, evCsr, evPrep;
    if (!sB) {
        cudaFuncSetAttribute(mma_gemm_kernel<128>,
                             cudaFuncAttributeMaxDynamicSharedMemorySize, smemA);
        cudaFuncSetAttribute(mma_gemm_kernel<64>,
                             cudaFuncAttributeMaxDynamicSharedMemorySize, smemA);
        cudaStreamCreateWithFlags(&sB, cudaStreamNonBlocking);
        cudaEventCreateWithFlags(&evFork, cudaEventDisableTiming);
        cudaEventCreateWithFlags(&evScan, cudaEventDisableTiming);
        cudaEventCreateWithFlags(&evCsr,  cudaEventDisableTiming);
        cudaEventCreateWithFlags(&evPrep, cudaEventDisableTiming);
    }

    const int gemmBlocks = (N + 127) / 128;
    const int aggBlocks = (N * 32 + 255) / 256;
    const int countBlocks = (E + 255) / 256;

    // fork side stream from the captured (legacy) stream
    cudaEventRecord(evFork, 0);
    cudaStreamWaitEvent(sB, evFork, 0);

    // side stream: CSR build (+W1 fragment build folded into count grid, R9 order)
    cudaMemsetAsync(count, 0, N * sizeof(int), sB);
    count_frag_kernel<<<countBlocks + 16, 256, 0, sB>>>(dst, E, count, countBlocks, W1, frag1);
    scan_kernel<<<1, 1024, 0, sB>>>(count, N, E, offs, dinv);
    cudaEventRecord(evScan, sB);
    scatter_kernel<<<countBlocks, 256, 0, sB>>>(src, dst, E, offs, count, csr);
    cudaEventRecord(evCsr, sB);

    // main stream: gemm128 after scan (needs frag1 + dinv for row prescale)
    cudaStreamWaitEvent(0, evScan, 0);
    mma_gemm_kernel<128><<<gemmBlocks, 256, smemA>>>(x, frag1, bufA, N, dinv);

    // side stream: bsum (needs CSR) + fused weight-chain collapse
    bsum_kernel<<<aggBlocks, 256, 0, sB>>>(offs, csr, dinv, bsum, N);
    prep_all_kernel<<<DOUTC + 1, 128, 0, sB>>>(Wp1, bp1, Wp2, bp2, W2, b2, W3, b3,
                                               v1, v2, fragC, bat, N, G, start);
    cudaEventRecord(evPrep, sB);

    // main stream: aggregation chain
    cudaStreamWaitEvent(0, evCsr, 0);
    agg128_kernel<<<aggBlocks, 256>>>(bufA, b1, ln1g, ln1b, ln2g, ln2b,
                                      bufB, N, offs, csr, dinv);
    cudaStreamWaitEvent(0, evPrep, 0);
    // gemm64 writes rows pre-scaled by dinv for the pure-sum agg chain
    mma_gemm_kernel<64><<<gemmBlocks, 256, smemA>>>(bufB, fragC, no, N, dinv);
    agg64_kernel<false><<<aggBlocks, 256>>>(no, bufA, N, offs, csr, dinv,
                                            nullptr, nullptr, nullptr);
    agg64_kernel<true><<<aggBlocks, 256>>>(bufA, no, N, offs, csr, dinv,
                                           bsum, v1, v2);

    // pooling + log_softmax
    pool_softmax_kernel<<<G, 256>>>(no, start, out);
}